// round 5
// baseline (speedup 1.0000x reference)
#include <cuda_runtime.h>
#include <math.h>

#define TOPK     64
#define NBINS    65536
#define NCHUNK   256
#define MAXCAND  4096
#define TPB      512          // 16 warps
#define NBLOCKS  148          // 1 per SM, persistent
#define DDIM     512
#define TILE_ROWS   16
#define STAGES      3
#define TILE_FLOATS (TILE_ROWS * DDIM)          // 8192 floats = 32 KB
#define TILE_F4     (TILE_FLOATS / 4)           // 2048 float4

__device__ float        g_alpha[262144];
__device__ unsigned int g_hist[NBINS];     // fkey >> 16
__device__ unsigned int g_coarse[NCHUNK];  // fkey >> 24
__device__ unsigned int g_done;            // zero-init; reset each run

// order-preserving float -> uint key
__device__ __forceinline__ unsigned int fkey(float f) {
    unsigned int b = __float_as_uint(f);
    return (b & 0x80000000u) ? ~b : (b | 0x80000000u);
}

__device__ __forceinline__ void cp_async16(void* smem_dst, const void* gmem_src) {
    unsigned int s = (unsigned int)__cvta_generic_to_shared(smem_dst);
    asm volatile("cp.async.cg.shared.global [%0], [%1], 16;\n" :: "r"(s), "l"(gmem_src));
}
__device__ __forceinline__ void cp_commit() {
    asm volatile("cp.async.commit_group;\n" ::: "memory");
}
template <int Npend>
__device__ __forceinline__ void cp_wait() {
    asm volatile("cp.async.wait_group %0;\n" :: "n"(Npend) : "memory");
}

// dynamic smem layout:
//   [0, 2048)                      : sv (512 floats)
//   [2048, 2048 + STAGES*32768)    : tile buffers
//   tail phase aliases the tile buffer region:
//     sval[MAXCAND] | sidx[MAXCAND] | r1[TPB] | r2[TPB]
#define SMEM_BYTES (2048 + STAGES * TILE_FLOATS * 4)

__global__ void __launch_bounds__(TPB, 1)
fused_kernel(const float* __restrict__ v,
             const float* __restrict__ vs,
             const float* __restrict__ scores,
             float* __restrict__ out, int N) {
    extern __shared__ char smem_raw[];
    float* sv  = (float*)smem_raw;
    float* buf = (float*)(smem_raw + 2048);

    const int tid  = threadIdx.x;
    const int lane = tid & 31;
    const int warp = tid >> 5;

    for (int i = tid; i < DDIM; i += TPB) sv[i] = v[i];
    __syncthreads();

    const float4* vv4 = (const float4*)sv;
    const float4 y0 = vv4[lane +  0];
    const float4 y1 = vv4[lane + 32];
    const float4 y2 = vv4[lane + 64];
    const float4 y3 = vv4[lane + 96];

    const int ntiles   = (N + TILE_ROWS - 1) / TILE_ROWS;
    const int mytiles  = (ntiles - blockIdx.x + gridDim.x - 1) / gridDim.x; // count of k with bid+k*grid < ntiles
    const long long totF4 = (long long)N * (DDIM / 4);

    // issue tile (local index k -> global tile bid + k*grid) into stage k%STAGES
    auto issue_tile = [&](int k) {
        if (k < mytiles) {
            int t = blockIdx.x + k * gridDim.x;
            float4*       dst = (float4*)(buf + (k % STAGES) * TILE_FLOATS);
            const float4* src = (const float4*)vs + (long long)t * TILE_F4;
            long long base = (long long)t * TILE_F4;
#pragma unroll
            for (int c = 0; c < 4; c++) {
                int j = tid + c * TPB;
                if (base + j < totF4) cp_async16(&dst[j], &src[j]);
            }
        }
        cp_commit();   // every thread, every slot: keeps group counts uniform
    };

    // prime the pipeline
    issue_tile(0);
    issue_tile(1);
    issue_tile(2);

    for (int k = 0; k < mytiles; k++) {
        cp_wait<STAGES - 1>();   // tile k resident
        __syncthreads();

        int t   = blockIdx.x + k * gridDim.x;
        int row = t * TILE_ROWS + warp;
        if (row < N) {
            const float4* bb = (const float4*)(buf + (k % STAGES) * TILE_FLOATS
                                               + warp * DDIM);
            float4 x0 = bb[lane +  0];
            float4 x1 = bb[lane + 32];
            float4 x2 = bb[lane + 64];
            float4 x3 = bb[lane + 96];
            float a0 = x0.x*y0.x + x0.y*y0.y + x0.z*y0.z + x0.w*y0.w;
            float a1 = x1.x*y1.x + x1.y*y1.y + x1.z*y1.z + x1.w*y1.w;
            float a2 = x2.x*y2.x + x2.y*y2.y + x2.z*y2.z + x2.w*y2.w;
            float a3 = x3.x*y3.x + x3.y*y3.y + x3.z*y3.z + x3.w*y3.w;
            float acc = (a0 + a1) + (a2 + a3);
#pragma unroll
            for (int o = 16; o; o >>= 1) acc += __shfl_xor_sync(0xffffffffu, acc, o);
            if (lane == 0) {
                g_alpha[row] = acc;
                unsigned int kk = fkey(acc);
                atomicAdd(&g_hist[kk >> 16], 1u);
                atomicAdd(&g_coarse[kk >> 24], 1u);
            }
        }
        __syncthreads();         // buffer k%STAGES free to refill
        issue_tile(k + STAGES);
    }
    cp_wait<0>();

    // ---------------- last-block election ------------------------------------
    __shared__ unsigned int s_isLast;
    __threadfence();
    __syncthreads();
    if (tid == 0)
        s_isLast = (atomicAdd(&g_done, 1u) == gridDim.x - 1) ? 1u : 0u;
    __syncthreads();
    if (!s_isLast) return;
    __threadfence();

    // ---------------- phase 2: threshold bin ---------------------------------
    __shared__ unsigned int sc[NCHUNK];
    __shared__ unsigned int sf[256];
    __shared__ unsigned int s_tb;
    __shared__ int s_chunk;
    __shared__ unsigned int s_above;
    if (tid < NCHUNK) sc[tid] = g_coarse[tid];
    __syncthreads();
    if (tid == 0) {
        unsigned int cum = 0;
        int c;
        for (c = 255; c >= 0; c--) {
            if (cum + sc[c] >= (unsigned int)TOPK) break;
            cum += sc[c];
        }
        if (c < 0) c = 0;
        s_chunk = c;
        s_above = cum;
    }
    __syncthreads();
    if (tid < 256) sf[tid] = g_hist[s_chunk * 256 + tid];
    __syncthreads();
    if (tid == 0) {
        unsigned int cum = s_above;
        int b;
        for (b = 255; b >= 0; b--) {
            cum += sf[b];
            if (cum >= (unsigned int)TOPK) break;
        }
        if (b < 0) b = 0;
        s_tb = (unsigned int)(s_chunk * 256 + b);
    }
    __syncthreads();
    unsigned int tb = s_tb;

    // ---------------- phase 3: scan alpha (L2-hot), candidates to smem -------
    // tail arrays alias the tile buffers (done with them now)
    float* sval = buf;
    int*   sidx = (int*)(buf + MAXCAND);
    float* r1   = (float*)(sidx + MAXCAND);
    float* r2   = r1 + TPB;

    __shared__ int s_cand;
    if (tid == 0) s_cand = 0;
    __syncthreads();

    int n4 = N >> 2;
    for (int i = tid; i < n4; i += TPB) {
        float4 a = ((const float4*)g_alpha)[i];
        int base = i << 2;
        if ((fkey(a.x) >> 16) >= tb) {
            int p = atomicAdd(&s_cand, 1);
            if (p < MAXCAND) { sval[p] = a.x; sidx[p] = base + 0; }
        }
        if ((fkey(a.y) >> 16) >= tb) {
            int p = atomicAdd(&s_cand, 1);
            if (p < MAXCAND) { sval[p] = a.y; sidx[p] = base + 1; }
        }
        if ((fkey(a.z) >> 16) >= tb) {
            int p = atomicAdd(&s_cand, 1);
            if (p < MAXCAND) { sval[p] = a.z; sidx[p] = base + 2; }
        }
        if ((fkey(a.w) >> 16) >= tb) {
            int p = atomicAdd(&s_cand, 1);
            if (p < MAXCAND) { sval[p] = a.w; sidx[p] = base + 3; }
        }
    }
    if (tid == 0) {
        for (int i = n4 << 2; i < N; i++) {
            float a = g_alpha[i];
            if ((fkey(a) >> 16) >= tb) {
                int p = atomicAdd(&s_cand, 1);
                if (p < MAXCAND) { sval[p] = a; sidx[p] = i; }
            }
        }
    }
    __syncthreads();
    int C = s_cand;
    if (C > MAXCAND) C = MAXCAND;

    // ---------------- phase 4: max, rank-select, softmax, weighted sum -------
    float m = -INFINITY;
    for (int i = tid; i < C; i += TPB) m = fmaxf(m, sval[i]);
    r1[tid] = m;
    __syncthreads();
    for (int s = TPB / 2; s; s >>= 1) {
        if (tid < s) r1[tid] = fmaxf(r1[tid], r1[tid + s]);
        __syncthreads();
    }
    m = r1[0];
    __syncthreads();

    float se = 0.f, acc = 0.f;
    for (int i = tid; i < C; i += TPB) {
        float vi = sval[i];
        unsigned int ki = fkey(vi);
        int rank = 0;
        for (int j = 0; j < C; j++) {
            unsigned int kj = fkey(sval[j]);
            rank += (kj > ki) || (kj == ki && j < i);
        }
        if (rank < TOPK) {
            float e = __expf(vi - m);
            se += e;
            acc += e * scores[sidx[i]];
        }
    }
    r1[tid] = se;
    r2[tid] = acc;
    __syncthreads();
    for (int s = TPB / 2; s; s >>= 1) {
        if (tid < s) {
            r1[tid] += r1[tid + s];
            r2[tid] += r2[tid + s];
        }
        __syncthreads();
    }
    if (tid == 0) out[0] = r2[0] / r1[0];

    // ---------------- phase 5: reset scratch for next graph replay -----------
    if (tid < NCHUNK) {
        if (sc[tid] != 0u) {
            uint4 z = make_uint4(0u, 0u, 0u, 0u);
            uint4* dst = (uint4*)&g_hist[tid * 256];
#pragma unroll
            for (int j = 0; j < 64; j++) dst[j] = z;
        }
        g_coarse[tid] = 0u;
    }
    if (tid == 0) g_done = 0u;
}

// ---------------- launch ------------------------------------------------------
extern "C" void kernel_launch(void* const* d_in, const int* in_sizes, int n_in,
                              void* d_out, int out_size) {
    const float* v      = (const float*)d_in[0];
    const float* vs     = (const float*)d_in[1];
    const float* scores = (const float*)d_in[2];
    float* out = (float*)d_out;
    int N = in_sizes[2];
    (void)n_in; (void)out_size;

    cudaFuncSetAttribute(fused_kernel,
                         cudaFuncAttributeMaxDynamicSharedMemorySize, SMEM_BYTES);
    fused_kernel<<<NBLOCKS, TPB, SMEM_BYTES>>>(v, vs, scores, out, N);
}

// round 6
// speedup vs baseline: 1.0067x; 1.0067x over previous
#include <cuda_runtime.h>
#include <math.h>

#define TOPK     64
#define NBINS    65536
#define NCHUNK   256
#define MAXCAND  4096
#define TPB      512          // 16 warps
#define NBLOCKS  148          // 1 per SM, persistent
#define DDIM     512
#define TILE_ROWS   16
#define STAGES      3
#define TILE_FLOATS (TILE_ROWS * DDIM)          // 8192 floats = 32 KB
#define TILE_F4     (TILE_FLOATS / 4)           // 2048 float4

__device__ float        g_alpha[262144];
__device__ unsigned int g_hist[NBINS];     // fkey >> 16
__device__ unsigned int g_coarse[NCHUNK];  // fkey >> 24
__device__ unsigned int g_done;            // zero-init; reset each run

// order-preserving float -> uint key
__device__ __forceinline__ unsigned int fkey(float f) {
    unsigned int b = __float_as_uint(f);
    return (b & 0x80000000u) ? ~b : (b | 0x80000000u);
}

__device__ __forceinline__ void cp_async16(void* smem_dst, const void* gmem_src) {
    unsigned int s = (unsigned int)__cvta_generic_to_shared(smem_dst);
    asm volatile("cp.async.cg.shared.global [%0], [%1], 16;\n" :: "r"(s), "l"(gmem_src));
}
__device__ __forceinline__ void cp_commit() {
    asm volatile("cp.async.commit_group;\n" ::: "memory");
}
template <int Npend>
__device__ __forceinline__ void cp_wait() {
    asm volatile("cp.async.wait_group %0;\n" :: "n"(Npend) : "memory");
}

// dynamic smem layout:
//   [0, 2048)                      : sv (512 floats)
//   [2048, 2048 + STAGES*32768)    : tile buffers
//   tail phase aliases the tile buffer region:
//     sval[MAXCAND] | sidx[MAXCAND] | r1[TPB] | r2[TPB]
#define SMEM_BYTES (2048 + STAGES * TILE_FLOATS * 4)

__global__ void __launch_bounds__(TPB, 1)
fused_kernel(const float* __restrict__ v,
             const float* __restrict__ vs,
             const float* __restrict__ scores,
             float* __restrict__ out, int N) {
    extern __shared__ char smem_raw[];
    float* sv  = (float*)smem_raw;
    float* buf = (float*)(smem_raw + 2048);

    const int tid  = threadIdx.x;
    const int lane = tid & 31;
    const int warp = tid >> 5;

    for (int i = tid; i < DDIM; i += TPB) sv[i] = v[i];
    __syncthreads();

    const float4* vv4 = (const float4*)sv;
    const float4 y0 = vv4[lane +  0];
    const float4 y1 = vv4[lane + 32];
    const float4 y2 = vv4[lane + 64];
    const float4 y3 = vv4[lane + 96];

    const int ntiles   = (N + TILE_ROWS - 1) / TILE_ROWS;
    const int mytiles  = (ntiles - blockIdx.x + gridDim.x - 1) / gridDim.x; // count of k with bid+k*grid < ntiles
    const long long totF4 = (long long)N * (DDIM / 4);

    // issue tile (local index k -> global tile bid + k*grid) into stage k%STAGES
    auto issue_tile = [&](int k) {
        if (k < mytiles) {
            int t = blockIdx.x + k * gridDim.x;
            float4*       dst = (float4*)(buf + (k % STAGES) * TILE_FLOATS);
            const float4* src = (const float4*)vs + (long long)t * TILE_F4;
            long long base = (long long)t * TILE_F4;
#pragma unroll
            for (int c = 0; c < 4; c++) {
                int j = tid + c * TPB;
                if (base + j < totF4) cp_async16(&dst[j], &src[j]);
            }
        }
        cp_commit();   // every thread, every slot: keeps group counts uniform
    };

    // prime the pipeline
    issue_tile(0);
    issue_tile(1);
    issue_tile(2);

    for (int k = 0; k < mytiles; k++) {
        cp_wait<STAGES - 1>();   // tile k resident
        __syncthreads();

        int t   = blockIdx.x + k * gridDim.x;
        int row = t * TILE_ROWS + warp;
        if (row < N) {
            const float4* bb = (const float4*)(buf + (k % STAGES) * TILE_FLOATS
                                               + warp * DDIM);
            float4 x0 = bb[lane +  0];
            float4 x1 = bb[lane + 32];
            float4 x2 = bb[lane + 64];
            float4 x3 = bb[lane + 96];
            float a0 = x0.x*y0.x + x0.y*y0.y + x0.z*y0.z + x0.w*y0.w;
            float a1 = x1.x*y1.x + x1.y*y1.y + x1.z*y1.z + x1.w*y1.w;
            float a2 = x2.x*y2.x + x2.y*y2.y + x2.z*y2.z + x2.w*y2.w;
            float a3 = x3.x*y3.x + x3.y*y3.y + x3.z*y3.z + x3.w*y3.w;
            float acc = (a0 + a1) + (a2 + a3);
#pragma unroll
            for (int o = 16; o; o >>= 1) acc += __shfl_xor_sync(0xffffffffu, acc, o);
            if (lane == 0) {
                g_alpha[row] = acc;
                unsigned int kk = fkey(acc);
                atomicAdd(&g_hist[kk >> 16], 1u);
                atomicAdd(&g_coarse[kk >> 24], 1u);
            }
        }
        __syncthreads();         // buffer k%STAGES free to refill
        issue_tile(k + STAGES);
    }
    cp_wait<0>();

    // ---------------- last-block election ------------------------------------
    __shared__ unsigned int s_isLast;
    __threadfence();
    __syncthreads();
    if (tid == 0)
        s_isLast = (atomicAdd(&g_done, 1u) == gridDim.x - 1) ? 1u : 0u;
    __syncthreads();
    if (!s_isLast) return;
    __threadfence();

    // ---------------- phase 2: threshold bin ---------------------------------
    __shared__ unsigned int sc[NCHUNK];
    __shared__ unsigned int sf[256];
    __shared__ unsigned int s_tb;
    __shared__ int s_chunk;
    __shared__ unsigned int s_above;
    if (tid < NCHUNK) sc[tid] = g_coarse[tid];
    __syncthreads();
    if (tid == 0) {
        unsigned int cum = 0;
        int c;
        for (c = 255; c >= 0; c--) {
            if (cum + sc[c] >= (unsigned int)TOPK) break;
            cum += sc[c];
        }
        if (c < 0) c = 0;
        s_chunk = c;
        s_above = cum;
    }
    __syncthreads();
    if (tid < 256) sf[tid] = g_hist[s_chunk * 256 + tid];
    __syncthreads();
    if (tid == 0) {
        unsigned int cum = s_above;
        int b;
        for (b = 255; b >= 0; b--) {
            cum += sf[b];
            if (cum >= (unsigned int)TOPK) break;
        }
        if (b < 0) b = 0;
        s_tb = (unsigned int)(s_chunk * 256 + b);
    }
    __syncthreads();
    unsigned int tb = s_tb;

    // ---------------- phase 3: scan alpha (L2-hot), candidates to smem -------
    // tail arrays alias the tile buffers (done with them now)
    float* sval = buf;
    int*   sidx = (int*)(buf + MAXCAND);
    float* r1   = (float*)(sidx + MAXCAND);
    float* r2   = r1 + TPB;

    __shared__ int s_cand;
    if (tid == 0) s_cand = 0;
    __syncthreads();

    int n4 = N >> 2;
    for (int i = tid; i < n4; i += TPB) {
        float4 a = ((const float4*)g_alpha)[i];
        int base = i << 2;
        if ((fkey(a.x) >> 16) >= tb) {
            int p = atomicAdd(&s_cand, 1);
            if (p < MAXCAND) { sval[p] = a.x; sidx[p] = base + 0; }
        }
        if ((fkey(a.y) >> 16) >= tb) {
            int p = atomicAdd(&s_cand, 1);
            if (p < MAXCAND) { sval[p] = a.y; sidx[p] = base + 1; }
        }
        if ((fkey(a.z) >> 16) >= tb) {
            int p = atomicAdd(&s_cand, 1);
            if (p < MAXCAND) { sval[p] = a.z; sidx[p] = base + 2; }
        }
        if ((fkey(a.w) >> 16) >= tb) {
            int p = atomicAdd(&s_cand, 1);
            if (p < MAXCAND) { sval[p] = a.w; sidx[p] = base + 3; }
        }
    }
    if (tid == 0) {
        for (int i = n4 << 2; i < N; i++) {
            float a = g_alpha[i];
            if ((fkey(a) >> 16) >= tb) {
                int p = atomicAdd(&s_cand, 1);
                if (p < MAXCAND) { sval[p] = a; sidx[p] = i; }
            }
        }
    }
    __syncthreads();
    int C = s_cand;
    if (C > MAXCAND) C = MAXCAND;

    // ---------------- phase 4: max, rank-select, softmax, weighted sum -------
    float m = -INFINITY;
    for (int i = tid; i < C; i += TPB) m = fmaxf(m, sval[i]);
    r1[tid] = m;
    __syncthreads();
    for (int s = TPB / 2; s; s >>= 1) {
        if (tid < s) r1[tid] = fmaxf(r1[tid], r1[tid + s]);
        __syncthreads();
    }
    m = r1[0];
    __syncthreads();

    float se = 0.f, acc = 0.f;
    for (int i = tid; i < C; i += TPB) {
        float vi = sval[i];
        unsigned int ki = fkey(vi);
        int rank = 0;
        for (int j = 0; j < C; j++) {
            unsigned int kj = fkey(sval[j]);
            rank += (kj > ki) || (kj == ki && j < i);
        }
        if (rank < TOPK) {
            float e = __expf(vi - m);
            se += e;
            acc += e * scores[sidx[i]];
        }
    }
    r1[tid] = se;
    r2[tid] = acc;
    __syncthreads();
    for (int s = TPB / 2; s; s >>= 1) {
        if (tid < s) {
            r1[tid] += r1[tid + s];
            r2[tid] += r2[tid + s];
        }
        __syncthreads();
    }
    if (tid == 0) out[0] = r2[0] / r1[0];

    // ---------------- phase 5: reset scratch for next graph replay -----------
    if (tid < NCHUNK) {
        if (sc[tid] != 0u) {
            uint4 z = make_uint4(0u, 0u, 0u, 0u);
            uint4* dst = (uint4*)&g_hist[tid * 256];
#pragma unroll
            for (int j = 0; j < 64; j++) dst[j] = z;
        }
        g_coarse[tid] = 0u;
    }
    if (tid == 0) g_done = 0u;
}

// ---------------- launch ------------------------------------------------------
extern "C" void kernel_launch(void* const* d_in, const int* in_sizes, int n_in,
                              void* d_out, int out_size) {
    const float* v      = (const float*)d_in[0];
    const float* vs     = (const float*)d_in[1];
    const float* scores = (const float*)d_in[2];
    float* out = (float*)d_out;
    int N = in_sizes[2];
    (void)n_in; (void)out_size;

    cudaFuncSetAttribute(fused_kernel,
                         cudaFuncAttributeMaxDynamicSharedMemorySize, SMEM_BYTES);
    fused_kernel<<<NBLOCKS, TPB, SMEM_BYTES>>>(v, vs, scores, out, N);
}

// round 7
// speedup vs baseline: 1.3450x; 1.3360x over previous
#include <cuda_runtime.h>
#include <math.h>

#define TOPK     64
#define NBINS    65536
#define NCHUNK   256
#define MAXCAND  4096
#define TPB      512           // 16 warps
#define NBLOCKS  296           // 2 per SM, persistent
#define DDIM     512

__device__ float        g_alpha[262144];
__device__ unsigned int g_hist[NBINS];     // fkey >> 16 (fine only; NO coarse hist)
__device__ unsigned int g_done;            // zero-init; reset each run

// order-preserving float -> uint key
__device__ __forceinline__ unsigned int fkey(float f) {
    unsigned int b = __float_as_uint(f);
    return (b & 0x80000000u) ? ~b : (b | 0x80000000u);
}

__global__ void __launch_bounds__(TPB, 2)
fused_kernel(const float* __restrict__ v,
             const float* __restrict__ vs,
             const float* __restrict__ scores,
             float* __restrict__ out, int N) {
    __shared__ float sv[DDIM];
    const int tid  = threadIdx.x;
    const int lane = tid & 31;
    const int warp = tid >> 5;

    for (int i = tid; i < DDIM; i += TPB) sv[i] = v[i];
    __syncthreads();

    const float4* vv4 = (const float4*)sv;
    const int gwarp  = blockIdx.x * (TPB / 32) + warp;
    const int nwarps = gridDim.x * (TPB / 32);

    // ---------------- phase 1: persistent matvec, 2-deep row pipeline --------
    int row = gwarp;
    float4 x0, x1, x2, x3;
    if (row < N) {
        const float4* p = (const float4*)(vs + (size_t)row * DDIM);
        x0 = p[lane +  0];
        x1 = p[lane + 32];
        x2 = p[lane + 64];
        x3 = p[lane + 96];
    }
    while (row < N) {
        int nrow = row + nwarps;
        float4 n0, n1, n2, n3;
        if (nrow < N) {
            const float4* p = (const float4*)(vs + (size_t)nrow * DDIM);
            n0 = p[lane +  0];
            n1 = p[lane + 32];
            n2 = p[lane + 64];
            n3 = p[lane + 96];
        }
        // v re-read from smem (keeps register count low; LDS is cheap)
        float4 y0 = vv4[lane +  0];
        float4 y1 = vv4[lane + 32];
        float4 y2 = vv4[lane + 64];
        float4 y3 = vv4[lane + 96];
        float a0 = x0.x*y0.x + x0.y*y0.y + x0.z*y0.z + x0.w*y0.w;
        float a1 = x1.x*y1.x + x1.y*y1.y + x1.z*y1.z + x1.w*y1.w;
        float a2 = x2.x*y2.x + x2.y*y2.y + x2.z*y2.z + x2.w*y2.w;
        float a3 = x3.x*y3.x + x3.y*y3.y + x3.z*y3.z + x3.w*y3.w;
        float acc = (a0 + a1) + (a2 + a3);
#pragma unroll
        for (int o = 16; o; o >>= 1) acc += __shfl_xor_sync(0xffffffffu, acc, o);
        if (lane == 0) {
            g_alpha[row] = acc;
            atomicAdd(&g_hist[fkey(acc) >> 16], 1u);   // fine hist only (~low contention)
        }
        x0 = n0; x1 = n1; x2 = n2; x3 = n3;
        row = nrow;
    }

    // ---------------- last-block election ------------------------------------
    __shared__ unsigned int s_isLast;
    __threadfence();
    __syncthreads();
    if (tid == 0)
        s_isLast = (atomicAdd(&g_done, 1u) == gridDim.x - 1) ? 1u : 0u;
    __syncthreads();
    if (!s_isLast) return;
    __threadfence();

    // ---------------- phase 2: coarse sums from fine hist, threshold bin -----
    // each thread sums 128 consecutive fine bins (= half a chunk of 256)
    __shared__ unsigned int sc[NCHUNK];          // per-chunk totals
    {
        const uint4* h4 = (const uint4*)g_hist;
        unsigned int s = 0;
        int base = tid * 32;                      // 32 uint4 = 128 bins
#pragma unroll 8
        for (int j = 0; j < 32; j++) {
            uint4 u = h4[base + j];
            s += u.x + u.y + u.z + u.w;
        }
        // two threads per chunk: reduce pairwise via shared
        __shared__ unsigned int half[TPB];
        half[tid] = s;
        __syncthreads();
        if (tid < NCHUNK) sc[tid] = half[2 * tid] + half[2 * tid + 1];
        __syncthreads();
    }

    __shared__ int s_chunk;
    __shared__ unsigned int s_above;
    __shared__ unsigned int s_tb;
    if (tid == 0) {
        unsigned int cum = 0;
        int c;
        for (c = 255; c >= 0; c--) {
            if (cum + sc[c] >= (unsigned int)TOPK) break;
            cum += sc[c];
        }
        if (c < 0) c = 0;
        s_chunk = c;
        s_above = cum;
    }
    __syncthreads();
    __shared__ unsigned int sf[256];
    if (tid < 256) sf[tid] = g_hist[s_chunk * 256 + tid];
    __syncthreads();
    if (tid == 0) {
        unsigned int cum = s_above;
        int b;
        for (b = 255; b >= 0; b--) {
            cum += sf[b];
            if (cum >= (unsigned int)TOPK) break;
        }
        if (b < 0) b = 0;
        s_tb = (unsigned int)(s_chunk * 256 + b);
    }
    __syncthreads();
    unsigned int tb = s_tb;

    // ---------------- phase 3: scan alpha (L2-hot), candidates to smem -------
    __shared__ float sval[MAXCAND];
    __shared__ int   sidx[MAXCAND];
    __shared__ int   s_cand;
    if (tid == 0) s_cand = 0;
    __syncthreads();

    int n4 = N >> 2;
    for (int i = tid; i < n4; i += TPB) {
        float4 a = ((const float4*)g_alpha)[i];
        int base = i << 2;
        if ((fkey(a.x) >> 16) >= tb) {
            int p = atomicAdd(&s_cand, 1);
            if (p < MAXCAND) { sval[p] = a.x; sidx[p] = base + 0; }
        }
        if ((fkey(a.y) >> 16) >= tb) {
            int p = atomicAdd(&s_cand, 1);
            if (p < MAXCAND) { sval[p] = a.y; sidx[p] = base + 1; }
        }
        if ((fkey(a.z) >> 16) >= tb) {
            int p = atomicAdd(&s_cand, 1);
            if (p < MAXCAND) { sval[p] = a.z; sidx[p] = base + 2; }
        }
        if ((fkey(a.w) >> 16) >= tb) {
            int p = atomicAdd(&s_cand, 1);
            if (p < MAXCAND) { sval[p] = a.w; sidx[p] = base + 3; }
        }
    }
    if (tid == 0) {
        for (int i = n4 << 2; i < N; i++) {
            float a = g_alpha[i];
            if ((fkey(a) >> 16) >= tb) {
                int p = atomicAdd(&s_cand, 1);
                if (p < MAXCAND) { sval[p] = a; sidx[p] = i; }
            }
        }
    }
    __syncthreads();
    int C = s_cand;
    if (C > MAXCAND) C = MAXCAND;

    // ---------------- phase 4: max, rank-select, softmax, weighted sum -------
    __shared__ float r1[TPB];
    __shared__ float r2[TPB];

    float m = -INFINITY;
    for (int i = tid; i < C; i += TPB) m = fmaxf(m, sval[i]);
    r1[tid] = m;
    __syncthreads();
    for (int s = TPB / 2; s; s >>= 1) {
        if (tid < s) r1[tid] = fmaxf(r1[tid], r1[tid + s]);
        __syncthreads();
    }
    m = r1[0];
    __syncthreads();

    float se = 0.f, acc = 0.f;
    for (int i = tid; i < C; i += TPB) {
        float vi = sval[i];
        unsigned int ki = fkey(vi);
        int rank = 0;
        for (int j = 0; j < C; j++) {
            unsigned int kj = fkey(sval[j]);
            rank += (kj > ki) || (kj == ki && j < i);
        }
        if (rank < TOPK) {
            float e = __expf(vi - m);
            se += e;
            acc += e * scores[sidx[i]];
        }
    }
    r1[tid] = se;
    r2[tid] = acc;
    __syncthreads();
    for (int s = TPB / 2; s; s >>= 1) {
        if (tid < s) {
            r1[tid] += r1[tid + s];
            r2[tid] += r2[tid + s];
        }
        __syncthreads();
    }
    if (tid == 0) out[0] = r2[0] / r1[0];

    // ---------------- phase 5: reset scratch for next graph replay -----------
    // zero only fine-hist chunks that were touched (sc[c] != 0)
    if (tid < NCHUNK) {
        if (sc[tid] != 0u) {
            uint4 z = make_uint4(0u, 0u, 0u, 0u);
            uint4* dst = (uint4*)&g_hist[tid * 256];
#pragma unroll
            for (int j = 0; j < 64; j++) dst[j] = z;
        }
    }
    if (tid == 0) g_done = 0u;
}

// ---------------- launch ------------------------------------------------------
extern "C" void kernel_launch(void* const* d_in, const int* in_sizes, int n_in,
                              void* d_out, int out_size) {
    const float* v      = (const float*)d_in[0];
    const float* vs     = (const float*)d_in[1];
    const float* scores = (const float*)d_in[2];
    float* out = (float*)d_out;
    int N = in_sizes[2];
    (void)n_in; (void)out_size;

    fused_kernel<<<NBLOCKS, TPB>>>(v, vs, scores, out, N);
}